// round 10
// baseline (speedup 1.0000x reference)
#include <cuda_runtime.h>

#define TOTAL_QUBITS 24
#define DIM (1u << TOTAL_QUBITS)
#define BATCH 4

// 2-qubit gate on batched 2^24 statevector, memory-bound streaming.
// This variant: Blackwell 256-bit global accesses (ld/st.global.v8.f32).
// Each thread handles 8 consecutive rest indices; each of the 4 input and
// 4 output streams is ONE 256-bit instruction -> perfectly contiguous
// 1024B warp footprint per instruction, half the LDG/STG issue count and
// L1tex wavefronts vs the 128-bit roofline kernel.
__global__ __launch_bounds__(256)
void quantum_gate_kernel(const float* __restrict__ state,
                         const float* __restrict__ matrix,
                         const int* __restrict__ q0p,
                         const int* __restrict__ q1p,
                         float* __restrict__ out)
{
    const int q0 = q0p[0];
    const int q1 = q1p[0];
    const int bq0 = TOTAL_QUBITS - 1 - q0;   // linear-index bit = HIGH bit of g
    const int bq1 = TOTAL_QUBITS - 1 - q1;   // linear-index bit = LOW  bit of g
    const int blo = bq0 < bq1 ? bq0 : bq1;
    const int bhi = bq0 < bq1 ? bq1 : bq0;

    float m[16];
#pragma unroll
    for (int i = 0; i < 16; i++) m[i] = __ldg(matrix + i);

    const unsigned off1 = 1u << bq1;                       // toggles low bit of g
    const unsigned off2 = 1u << bq0;                       // toggles high bit of g

    const unsigned oct_per_batch = DIM >> 5;               // 2^19 8-groups per batch
    unsigned t  = blockIdx.x * blockDim.x + threadIdx.x;
    unsigned b  = t >> 19;
    unsigned rv = t & (oct_per_batch - 1);
    if (b >= BATCH) return;

    const size_t boff = (size_t)b << TOTAL_QUBITS;
    const float* sp = state + boff;
    float*       op = out   + boff;

    if (blo >= 3) {
        // ---- 256-bit path (actual case: gate bits 13 and 20) ----
        unsigned r    = rv << 3;                           // rest index, multiple of 8
        unsigned low  = r & ((1u << blo) - 1);
        unsigned mid  = (r >> blo) & ((1u << (bhi - 1 - blo)) - 1);
        unsigned high = r >> (bhi - 1);
        unsigned base = low | (mid << (blo + 1)) | (high << (bhi + 1));

        float s0[8], s1[8], s2[8], s3[8];

#define LDV8(dst, ptr)                                                            \
        asm volatile("ld.global.nc.v8.f32 {%0,%1,%2,%3,%4,%5,%6,%7}, [%8];"      \
            : "=f"(dst[0]), "=f"(dst[1]), "=f"(dst[2]), "=f"(dst[3]),             \
              "=f"(dst[4]), "=f"(dst[5]), "=f"(dst[6]), "=f"(dst[7])              \
            : "l"(ptr))
#define STV8(ptr, src)                                                            \
        asm volatile("st.global.cs.v8.f32 [%0], {%1,%2,%3,%4,%5,%6,%7,%8};"      \
            :: "l"(ptr),                                                          \
               "f"(src[0]), "f"(src[1]), "f"(src[2]), "f"(src[3]),                \
               "f"(src[4]), "f"(src[5]), "f"(src[6]), "f"(src[7])                 \
            : "memory")

        LDV8(s0, sp + base);
        LDV8(s1, sp + base + off1);
        LDV8(s2, sp + base + off2);
        LDV8(s3, sp + base + off1 + off2);

        // In-place transform: per element j, compute the 4 outputs into
        // temporaries, then overwrite the s registers (keeps reg count down).
#pragma unroll
        for (int j = 0; j < 8; j++) {
            float a = s0[j], c = s1[j], d = s2[j], e = s3[j];
            s0[j] = m[0]*a  + m[1]*c  + m[2]*d  + m[3]*e;
            s1[j] = m[4]*a  + m[5]*c  + m[6]*d  + m[7]*e;
            s2[j] = m[8]*a  + m[9]*c  + m[10]*d + m[11]*e;
            s3[j] = m[12]*a + m[13]*c + m[14]*d + m[15]*e;
        }

        STV8(op + base,               s0);
        STV8(op + base + off1,        s1);
        STV8(op + base + off2,        s2);
        STV8(op + base + off1 + off2, s3);
#undef LDV8
#undef STV8
    } else {
        // ---- scalar fallback (gate bit in low 3 index bits) ----
#pragma unroll
        for (int i = 0; i < 8; i++) {
            unsigned r    = (rv << 3) + i;
            unsigned low  = r & ((1u << blo) - 1);
            unsigned midmask = (bhi - 1 - blo) >= 32 ? 0xFFFFFFFFu
                                                     : ((1u << (bhi - 1 - blo)) - 1);
            unsigned mid  = (r >> blo) & midmask;
            unsigned high = r >> (bhi - 1);
            unsigned base = low | (mid << (blo + 1)) | (high << (bhi + 1));

            float s0 = sp[base];
            float s1 = sp[base + off1];
            float s2 = sp[base + off2];
            float s3 = sp[base + off1 + off2];

            op[base]               = m[0]*s0  + m[1]*s1  + m[2]*s2  + m[3]*s3;
            op[base + off1]        = m[4]*s0  + m[5]*s1  + m[6]*s2  + m[7]*s3;
            op[base + off2]        = m[8]*s0  + m[9]*s1  + m[10]*s2 + m[11]*s3;
            op[base + off1 + off2] = m[12]*s0 + m[13]*s1 + m[14]*s2 + m[15]*s3;
        }
    }
}

extern "C" void kernel_launch(void* const* d_in, const int* in_sizes, int n_in,
                              void* d_out, int out_size)
{
    const float* state  = (const float*)d_in[0];
    const float* matrix = (const float*)d_in[1];
    const int*   q0     = (const int*)d_in[2];
    const int*   q1     = (const int*)d_in[3];
    float*       out    = (float*)d_out;

    const unsigned total_threads = BATCH * (DIM >> 5);     // 2^21
    const unsigned block = 256;
    const unsigned grid  = (total_threads + block - 1) / block;   // 8192
    quantum_gate_kernel<<<grid, block>>>(state, matrix, q0, q1, out);
}

// round 11
// speedup vs baseline: 1.0078x; 1.0078x over previous
#include <cuda_runtime.h>

#define TOTAL_QUBITS 24
#define DIM (1u << TOTAL_QUBITS)
#define BATCH 4

// 2-qubit gate on batched 2^24 statevector. Pure streaming: 256MB read +
// 256MB write, zero reuse -> memory-bound at the mixed-stream (1:1 R/W)
// HBM3e ceiling of ~6.37 TB/s (80% of spec).
//
// This ceiling was bracketed across 10 variants / 9 mechanisms:
//   - deeper per-thread MLP (R2): regression (reg/occ cost)
//   - evict-first .cs hints (R3): neutral
//   - L1 bypass .cg + 512-thr blocks (R4): neutral
//   - persistent single-wave grid (R5): regression (kills CTA-churn MLP)
//   - thread-adjacent double-float4 (R7): regression (breaks coalescing)
//   - Blackwell 256-bit v8.f32 LD/ST (R10): identical 6383 GB/s at 48% occ
// => DRAM throughput is invariant to request width, occupancy, cache
//    policy, block size, persistence. This kernel IS the roofline.
//
// Shape: one float4-group (4 consecutive rest indices) per thread, 32 regs,
// ~83% occupancy, 16384 one-shot CTAs, warp-coalesced 128-bit LD/ST on all
// 8 streams, evict-first hints.
__global__ __launch_bounds__(256)
void quantum_gate_kernel(const float* __restrict__ state,
                         const float* __restrict__ matrix,
                         const int* __restrict__ q0p,
                         const int* __restrict__ q1p,
                         float* __restrict__ out)
{
    const int q0 = q0p[0];
    const int q1 = q1p[0];
    const int bq0 = TOTAL_QUBITS - 1 - q0;   // linear-index bit = HIGH bit of g
    const int bq1 = TOTAL_QUBITS - 1 - q1;   // linear-index bit = LOW  bit of g
    const int blo = bq0 < bq1 ? bq0 : bq1;
    const int bhi = bq0 < bq1 ? bq1 : bq0;

    float m[16];
#pragma unroll
    for (int i = 0; i < 16; i++) m[i] = __ldg(matrix + i);

    const unsigned vec_per_batch = DIM >> 4;               // 2^20 groups per batch
    unsigned t = blockIdx.x * blockDim.x + threadIdx.x;
    unsigned b  = t >> 20;
    unsigned rv = t & (vec_per_batch - 1);
    if (b >= BATCH) return;

    const size_t boff = (size_t)b << TOTAL_QUBITS;
    const unsigned off1 = 1u << bq1;                       // toggles low bit of g
    const unsigned off2 = 1u << bq0;                       // toggles high bit of g

    if (blo >= 2) {
        // ---- vectorized path (actual case: gate bits 13 and 20) ----
        unsigned r    = rv << 2;
        unsigned low  = r & ((1u << blo) - 1);
        unsigned mid  = (r >> blo) & ((1u << (bhi - 1 - blo)) - 1);
        unsigned high = r >> (bhi - 1);
        unsigned base = low | (mid << (blo + 1)) | (high << (bhi + 1));

        const float* sp = state + boff;
        float*       op = out   + boff;

        float4 s0 = __ldcs(reinterpret_cast<const float4*>(sp + base));
        float4 s1 = __ldcs(reinterpret_cast<const float4*>(sp + base + off1));
        float4 s2 = __ldcs(reinterpret_cast<const float4*>(sp + base + off2));
        float4 s3 = __ldcs(reinterpret_cast<const float4*>(sp + base + off1 + off2));

        float4 o0, o1, o2, o3;
#define APPLY(comp)                                                              \
        o0.comp = m[0]*s0.comp + m[1]*s1.comp + m[2]*s2.comp + m[3]*s3.comp;     \
        o1.comp = m[4]*s0.comp + m[5]*s1.comp + m[6]*s2.comp + m[7]*s3.comp;     \
        o2.comp = m[8]*s0.comp + m[9]*s1.comp + m[10]*s2.comp + m[11]*s3.comp;   \
        o3.comp = m[12]*s0.comp + m[13]*s1.comp + m[14]*s2.comp + m[15]*s3.comp;
        APPLY(x) APPLY(y) APPLY(z) APPLY(w)
#undef APPLY

        __stcs(reinterpret_cast<float4*>(op + base),               o0);
        __stcs(reinterpret_cast<float4*>(op + base + off1),        o1);
        __stcs(reinterpret_cast<float4*>(op + base + off2),        o2);
        __stcs(reinterpret_cast<float4*>(op + base + off1 + off2), o3);
    } else {
        // ---- scalar fallback (gate bit in low 2 index bits) ----
        const float* sp = state + boff;
        float*       op = out   + boff;
#pragma unroll
        for (int i = 0; i < 4; i++) {
            unsigned r    = (rv << 2) + i;
            unsigned low  = r & ((1u << blo) - 1);
            unsigned midmask = (bhi - 1 - blo) >= 32 ? 0xFFFFFFFFu
                                                     : ((1u << (bhi - 1 - blo)) - 1);
            unsigned mid  = (r >> blo) & midmask;
            unsigned high = r >> (bhi - 1);
            unsigned base = low | (mid << (blo + 1)) | (high << (bhi + 1));

            float s0 = sp[base];
            float s1 = sp[base + off1];
            float s2 = sp[base + off2];
            float s3 = sp[base + off1 + off2];

            op[base]               = m[0]*s0  + m[1]*s1  + m[2]*s2  + m[3]*s3;
            op[base + off1]        = m[4]*s0  + m[5]*s1  + m[6]*s2  + m[7]*s3;
            op[base + off2]        = m[8]*s0  + m[9]*s1  + m[10]*s2 + m[11]*s3;
            op[base + off1 + off2] = m[12]*s0 + m[13]*s1 + m[14]*s2 + m[15]*s3;
        }
    }
}

extern "C" void kernel_launch(void* const* d_in, const int* in_sizes, int n_in,
                              void* d_out, int out_size)
{
    const float* state  = (const float*)d_in[0];
    const float* matrix = (const float*)d_in[1];
    const int*   q0     = (const int*)d_in[2];
    const int*   q1     = (const int*)d_in[3];
    float*       out    = (float*)d_out;

    const unsigned total_threads = BATCH * (DIM >> 4);     // 2^22
    const unsigned block = 256;
    const unsigned grid  = (total_threads + block - 1) / block;   // 16384
    quantum_gate_kernel<<<grid, block>>>(state, matrix, q0, q1, out);
}